// round 4
// baseline (speedup 1.0000x reference)
#include <cuda_runtime.h>
#include <cuda_bf16.h>
#include <math.h>

// Problem constants (fixed by the reference)
#define BB 4
#define TT 512
#define TP 1024
#define CC 32
#define KK 128
#define EPSF 2.220446049250313e-16f

// ---------------- device scratch (no allocations allowed) ----------------
__device__ float g_PA[CC * CC];        // softplus(alpha)[e][c]
__device__ float g_PD[CC * CC];        // softplus(delta)[e][c] + EPS
__device__ float g_NPD[CC * CC];       // -(softplus(delta)+EPS)
__device__ float g_spmu[CC];           // softplus(mu)
__device__ float g_pfine[KK];          // fine probs
__device__ int   g_obase[BB * CC];     // per-(b,e) start slot in grouped time list
__device__ int   g_gbase[BB * CC];     // per-(b,e) start row in GP table
__device__ int   g_n[BB * CC];         // group sizes
__device__ float g_gtg[BB * TT];       // times grouped by event type (stable order)
__device__ int   g_cnt[BB * (TT + 1) * CC];        // cnt[b][J][e] = #events of type e among first J
__device__ float g_GP[BB * (TT + CC) * CC];        // GP rows: pa[e][c] * prefix-sum of exp(pd*pt)

__device__ __forceinline__ float softplusf(float x) {
    return log1pf(expf(x));
}

// ---------------- kernel A: tables, probs, grouping metadata ----------------
__global__ __launch_bounds__(256) void setup_kernel(
    const int*   __restrict__ past_event,   // [B,T]
    const float* __restrict__ past_time,    // [B,T]
    const float* __restrict__ mu,           // [C]
    const float* __restrict__ alpha,        // [C,C]
    const float* __restrict__ delta,        // [C,C]
    const float* __restrict__ cf,           // [K]
    const int*   __restrict__ ftc)          // [K]
{
    __shared__ int   sh_ev[BB * TT];     // 8 KB
    __shared__ int   sh_n[BB * CC];
    __shared__ float sh_e[KK];
    __shared__ float sh_den[CC];
    __shared__ float sh_max;
    const int tid = threadIdx.x;

    // Phase 1: softplus tables, mu, load events, max(cf)
    for (int i = tid; i < CC * CC; i += 256) {
        g_PA[i] = softplusf(alpha[i]);
        float pd = softplusf(delta[i]) + EPSF;
        g_PD[i] = pd;
        g_NPD[i] = -pd;
    }
    if (tid < CC) g_spmu[tid] = softplusf(mu[tid]);
    for (int i = tid; i < BB * TT; i += 256) sh_ev[i] = past_event[i];
    if (tid == 0) {
        float m = cf[0];
        for (int k = 1; k < KK; k++) m = fmaxf(m, cf[k]);
        sh_max = m;
    }
    __syncthreads();

    // Phase 2: exp(cf - max); build cnt table (128 independent chains)
    if (tid < KK) sh_e[tid] = expf(cf[tid] - sh_max);
    if (tid < BB * CC) {
        const int b = tid >> 5, e = tid & 31;
        const int* evb = &sh_ev[b * TT];
        int base = (b * (TT + 1)) * CC + e;
        int c = 0;
        for (int t = 0; t < TT; t++) {
            g_cnt[base + t * CC] = c;
            c += (evb[t] == e) ? 1 : 0;
        }
        g_cnt[base + TT * CC] = c;
        sh_n[tid] = c;
    }
    __syncthreads();

    // Phase 3: segment denominators; per-batch prefixes
    if (tid < CC) {
        float d = 0.f;
        for (int k = 0; k < KK; k++)
            if (ftc[k] == tid) d += sh_e[k];
        sh_den[tid] = d;
    }
    if (tid < BB) {
        const int b = tid;
        int ob = 0, gb = b * (TT + CC);
        for (int e = 0; e < CC; e++) {
            int n = sh_n[b * CC + e];
            g_obase[b * CC + e] = ob;
            g_gbase[b * CC + e] = gb;
            g_n[b * CC + e] = n;
            ob += n;
            gb += n + 1;
        }
    }
    __syncthreads();

    // Phase 4: fine probs; scatter times into grouped order (parallel via cnt)
    if (tid < KK) g_pfine[tid] = sh_e[tid] / sh_den[ftc[tid]];
    for (int i = tid; i < BB * TT; i += 256) {
        int b = i >> 9, t = i & (TT - 1);
        int e = sh_ev[i];
        int slot = g_obase[b * CC + e] + g_cnt[(b * (TT + 1) + t) * CC + e];
        g_gtg[b * TT + slot] = past_time[i];
    }
}

// ---------------- kernel B: per-(b,e) prefix sums of exp(pd*pt), pa folded ----------------
__global__ __launch_bounds__(32) void prefix_kernel()
{
    const int blk = blockIdx.x;            // 0..127 -> (b,e)
    const int b = blk >> 5, e = blk & 31;
    const int lane = threadIdx.x;          // = c
    const float pd = g_PD[e * CC + lane];
    const float pa = g_PA[e * CC + lane];
    const int n = g_n[b * CC + e];
    const int ob = g_obase[b * CC + e];
    const int base = g_gbase[b * CC + e] * CC;

    g_GP[base + lane] = 0.f;               // j = 0 row
    float s = 0.f;
    for (int j = 0; j < n; j++) {
        float pt = g_gtg[b * TT + ob + j];
        s += __expf(pd * pt);
        g_GP[base + (j + 1) * CC + lane] = s * pa;
    }
}

// ---------------- kernel C: main evaluation. warp per (b,tp), lane = c ----------------
__global__ __launch_bounds__(256) void main_kernel(
    const float* __restrict__ past_time,    // [B,T]
    const float* __restrict__ time_tensor,  // [B,TP]
    const int*   __restrict__ ftc,          // [K]
    float*       __restrict__ out)          // [B,TP,K]
{
    __shared__ float sh_npd[CC * CC];   // 4 KB
    __shared__ float sh_t[TT];          // 2 KB (batch's sorted event times)
    __shared__ int   sh_gbase[CC];
    __shared__ float sh_spmu[CC];
    __shared__ float sh_pf[KK];
    __shared__ int   sh_ftc[KK];
    __shared__ float sh_acc[8][CC];

    const int b = blockIdx.y;
    const int tid = threadIdx.x;
    for (int i = tid; i < CC * CC; i += 256) sh_npd[i] = g_NPD[i];
    for (int i = tid; i < TT; i += 256)      sh_t[i] = past_time[b * TT + i];
    if (tid < CC) { sh_gbase[tid] = g_gbase[b * CC + tid]; sh_spmu[tid] = g_spmu[tid]; }
    if (tid < KK) { sh_pf[tid] = g_pfine[tid]; sh_ftc[tid] = ftc[tid]; }
    __syncthreads();

    const int w = tid >> 5, lane = tid & 31;
    const int tp = blockIdx.x * 8 + w;
    const float tt = time_tensor[b * TP + tp];

    // warp-uniform binary search: J = #events with (tt - pt) > EPS (monotone in t)
    int lo = 0, hi = TT;
    while (lo < hi) {
        int mid = (lo + hi) >> 1;
        if (tt - sh_t[mid] > EPSF) lo = mid + 1; else hi = mid;
    }
    const int J = lo;

    // lane l pre-resolves the GP row for event-type e = l
    const int jl = g_cnt[(b * (TT + 1) + J) * CC + lane];
    const int rowl = sh_gbase[lane] + jl;

    float acc = 0.f;
#pragma unroll
    for (int e = 0; e < CC; e++) {
        int row = __shfl_sync(0xffffffffu, rowl, e);
        float gp = g_GP[row * CC + lane];              // coalesced 128B, L2 resident
        float ex = __expf(sh_npd[e * CC + lane] * tt); // MUFU
        acc = fmaf(ex, gp, acc);
    }

    sh_acc[w][lane] = acc;
    __syncwarp();
    float* o = out + (b * TP + tp) * KK;
#pragma unroll
    for (int i = 0; i < 4; i++) {
        int k = lane + 32 * i;
        int c = sh_ftc[k];
        o[k] = (sh_acc[w][c] + sh_spmu[c]) * sh_pf[k];
    }
}

// ---------------- launch ----------------
extern "C" void kernel_launch(void* const* d_in, const int* in_sizes, int n_in,
                              void* d_out, int out_size)
{
    const int*   past_event  = (const int*)  d_in[0];
    const float* past_time   = (const float*)d_in[1];
    const float* time_tensor = (const float*)d_in[2];
    const float* mu          = (const float*)d_in[3];
    const float* alpha       = (const float*)d_in[4];
    const float* delta       = (const float*)d_in[5];
    const float* cf_logits   = (const float*)d_in[6];
    const int*   ftc         = (const int*)  d_in[7];
    float* out = (float*)d_out;

    setup_kernel<<<1, 256>>>(past_event, past_time, mu, alpha, delta, cf_logits, ftc);
    prefix_kernel<<<BB * CC, 32>>>();
    main_kernel<<<dim3(TP / 8, BB), 256>>>(past_time, time_tensor, ftc, out);
}